// round 5
// baseline (speedup 1.0000x reference)
#include <cuda_runtime.h>
#include <math.h>

// ---------------------------------------------------------------------------
// Multi-view edge photometric loss.
// Inputs: 0 start(N,3) 1 end(N,3) 2 imgs(5,H,W) 3 trans(S,3,4) 4 K(3,3)
//         5 coords_x(P) 6 coords_y(P) 7 edge_idx(P,i32) 8 num_per_edge(N,i32)
// coords recomputed analytically. Output f32:
//  loss(S,N) | mask(S,N) | black(N) | p2d1(P,2) | p2d2(S,P,2)
// ---------------------------------------------------------------------------

#define MAXE 6144
#define NS 4
#define NHV2 20

__device__ float g_params[5 * MAXE * 8];
__device__ int   g_begin[MAXE];

// ---------------- fused prep: block 0 scans, others do edge params ---------
__device__ __forceinline__ void store_prm(int cam, int e, int nE,
                                          float p0x, float p0y,
                                          float dx, float dy, float upscale)
{
    float cx = dy, cy = -dx;
    float nrm = sqrtf(cx * cx + cy * cy);
    float sc = upscale / (nrm + 1e-6f);
    float* p = &g_params[((size_t)cam * nE + e) * 8];
    p[0] = p0x; p[1] = p0y; p[2] = dx; p[3] = dy; p[4] = cx * sc; p[5] = cy * sc;
}

__global__ void prep_kernel(const int* __restrict__ npe,
                            const float* __restrict__ sp,
                            const float* __restrict__ ep,
                            const float* __restrict__ K,
                            const float* __restrict__ trans,
                            int n_edges, int num_src, float upscale)
{
    if (blockIdx.x == 0) {
        __shared__ int ssum[256];
        int tid = threadIdx.x;
        int chunk = (n_edges + 255) / 256;
        int lo = min(tid * chunk, n_edges);
        int hi = min(lo + chunk, n_edges);
        int local = 0;
        for (int i = lo; i < hi; i++) local += npe[i];
        ssum[tid] = local;
        __syncthreads();
        for (int d = 1; d < 256; d <<= 1) {
            int t = (tid >= d) ? ssum[tid - d] : 0;
            __syncthreads();
            ssum[tid] += t;
            __syncthreads();
        }
        int run = ssum[tid] - local;
        for (int i = lo; i < hi; i++) { g_begin[i] = run; run += npe[i]; }
        return;
    }
    int e = (blockIdx.x - 1) * blockDim.x + threadIdx.x;
    if (e >= n_edges) return;
    float sx = sp[3 * e], sy = sp[3 * e + 1], sz = sp[3 * e + 2];
    float tx = ep[3 * e], ty = ep[3 * e + 1], tz = ep[3 * e + 2];
    {
        float pzs = K[6] * sx + K[7] * sy + K[8] * sz;
        float us  = (K[0] * sx + K[1] * sy + K[2] * sz) / (pzs + 1e-6f);
        float vs  = (K[3] * sx + K[4] * sy + K[5] * sz) / (pzs + 1e-6f);
        float pzt = K[6] * tx + K[7] * ty + K[8] * tz;
        float ut  = (K[0] * tx + K[1] * ty + K[2] * tz) / (pzt + 1e-6f);
        float vt  = (K[3] * tx + K[4] * ty + K[5] * tz) / (pzt + 1e-6f);
        store_prm(0, e, n_edges, us, vs, ut - us, vt - vs, upscale);
    }
    for (int s = 0; s < num_src; s++) {
        const float* T = trans + 12 * s;
        float pzs = T[8] * sx + T[9] * sy + T[10] * sz + T[11];
        float us  = (T[0] * sx + T[1] * sy + T[2] * sz + T[3]) / (pzs + 1e-6f);
        float vs  = (T[4] * sx + T[5] * sy + T[6] * sz + T[7]) / (pzs + 1e-6f);
        float pzt = T[8] * tx + T[9] * ty + T[10] * tz + T[11];
        float ut  = (T[0] * tx + T[1] * ty + T[2] * tz + T[3]) / (pzt + 1e-6f);
        float vt  = (T[4] * tx + T[5] * ty + T[6] * tz + T[7]) / (pzt + 1e-6f);
        store_prm(1 + s, e, n_edges, us, vs, ut - us, vt - vs, upscale);
    }
}

// --------------------------- bilinear sample -------------------------------
__device__ __forceinline__ float bilerp(const float* __restrict__ img,
                                        float u, float v, int W, int H)
{
    float x = u * (float)W - 0.5f;
    float y = v * (float)H - 0.5f;
    float x0f = floorf(x), y0f = floorf(y);
    float wx = x - x0f, wy = y - y0f;
    int x0i = min(max((int)x0f, 0), W - 1);
    int x1i = min(x0i + 1, W - 1);
    int y0i = min(max((int)y0f, 0), H - 1);
    int y1i = min(y0i + 1, H - 1);
    const float* r0 = img + (size_t)y0i * W;
    const float* r1 = img + (size_t)y1i * W;
    float v00 = __ldg(r0 + x0i), v01 = __ldg(r0 + x1i);
    float v10 = __ldg(r1 + x0i), v11 = __ldg(r1 + x1i);
    float top = fmaf(wx, v01 - v00, v00);
    float bot = fmaf(wx, v11 - v10, v10);
    return fmaf(wy, bot - top, top);
}

// ----------- point kernel: block/edge, 128 thr, 2 points/thread ------------
__global__ void __launch_bounds__(128, 12)
point_kernel(const float* __restrict__ imgs,
             const int* __restrict__ npe,
             float* __restrict__ out_loss, float* __restrict__ out_mask,
             float* __restrict__ out_black,
             float* __restrict__ out_p2d1, float* __restrict__ out_p2d2,
             int W, int H, int n_edges, int P)
{
    int e = blockIdx.x;
    int tid = threadIdx.x;

    __shared__ float sprm[30];     // 5 cams x 6 params, block-uniform
    __shared__ float redf[4][5];
    __shared__ unsigned redm[4];

    if (tid < 30) {
        int cam = tid / 6, j = tid - cam * 6;
        sprm[tid] = g_params[((size_t)cam * n_edges + e) * 8 + j];
    }
    __syncthreads();

    int b = g_begin[e];
    int n = npe[e];
    float inv_nh1 = 1.0f / (float)(n / NHV2 - 1);
    const size_t imgHW = (size_t)W * H;

    float ls0 = 0.f, ls1 = 0.f, ls2 = 0.f, ls3 = 0.f;
    float bc = 0.f;
    unsigned m = (1u << NS) - 1u;

    float4* o1 = reinterpret_cast<float4*>(out_p2d1) + (b >> 1);
    float4* o2 = reinterpret_cast<float4*>(out_p2d2) + (b >> 1);
    size_t strideP = (size_t)P >> 1;

    int npair = n >> 1;  // n multiple of 20
    for (int r = tid; r < npair; r += 128) {
        int h  = r / 10;
        int jj = r - h * 10;
        float cx = (float)h * inv_nh1;
        float base = (float)(2 * jj + ((jj < 5) ? -9 : -10));
        float cy0 = base * (1.0f / 9.0f);
        float cy1 = (base + 1.0f) * (1.0f / 9.0f);

        // reference camera (params via broadcast LDS)
        float u0 = fmaf(sprm[2], cx, fmaf(sprm[4], cy0, sprm[0]));
        float v0 = fmaf(sprm[3], cx, fmaf(sprm[5], cy0, sprm[1]));
        float u1 = fmaf(sprm[2], cx, fmaf(sprm[4], cy1, sprm[0]));
        float v1 = fmaf(sprm[3], cx, fmaf(sprm[5], cy1, sprm[1]));
        bool vm1a = (u0 > 0.f) & (u0 < 1.f) & (v0 > 0.f) & (v0 < 1.f);
        bool vm1b = (u1 > 0.f) & (u1 < 1.f) & (v1 > 0.f) & (v1 < 1.f);
        u0 = fminf(fmaxf(u0, 0.f), 0.999999f);
        v0 = fminf(fmaxf(v0, 0.f), 0.999999f);
        u1 = fminf(fmaxf(u1, 0.f), 0.999999f);
        v1 = fminf(fmaxf(v1, 0.f), 0.999999f);
        o1[r] = make_float4(u0, v0, u1, v1);
        float s1a = bilerp(imgs, u0, v0, W, H);
        float s1b = bilerp(imgs, u1, v1, W, H);
        if (s1a < 0.01f) bc += 1.f;
        if (s1b < 0.01f) bc += 1.f;

#pragma unroll
        for (int s = 0; s < NS; s++) {
            const float* q = &sprm[(s + 1) * 6];
            float ua = fmaf(q[2], cx, fmaf(q[4], cy0, q[0]));
            float va = fmaf(q[3], cx, fmaf(q[5], cy0, q[1]));
            float ub = fmaf(q[2], cx, fmaf(q[4], cy1, q[0]));
            float vb = fmaf(q[3], cx, fmaf(q[5], cy1, q[1]));
            bool oka = vm1a & (ua > 0.f) & (ua < 1.f) & (va > 0.f) & (va < 1.f);
            bool okb = vm1b & (ub > 0.f) & (ub < 1.f) & (vb > 0.f) & (vb < 1.f);
            ua = fminf(fmaxf(ua, 0.f), 0.999999f);
            va = fminf(fmaxf(va, 0.f), 0.999999f);
            ub = fminf(fmaxf(ub, 0.f), 0.999999f);
            vb = fminf(fmaxf(vb, 0.f), 0.999999f);
            o2[(size_t)s * strideP + r] = make_float4(ua, va, ub, vb);
            const float* img = imgs + (size_t)(s + 1) * imgHW;
            float s2a = bilerp(img, ua, va, W, H);
            float s2b = bilerp(img, ub, vb, W, H);
            float da = s2a - s1a;
            float db = s2b - s1b;
            float acc = fmaf(da, da, db * db);
            if (s == 0) ls0 += acc;
            else if (s == 1) ls1 += acc;
            else if (s == 2) ls2 += acc;
            else ls3 += acc;
            if (!(oka && okb)) m &= ~(1u << s);
        }
    }

    // warp + block reduce
#pragma unroll
    for (int off = 16; off > 0; off >>= 1) {
        ls0 += __shfl_down_sync(0xFFFFFFFFu, ls0, off);
        ls1 += __shfl_down_sync(0xFFFFFFFFu, ls1, off);
        ls2 += __shfl_down_sync(0xFFFFFFFFu, ls2, off);
        ls3 += __shfl_down_sync(0xFFFFFFFFu, ls3, off);
        bc  += __shfl_down_sync(0xFFFFFFFFu, bc, off);
        m   &= __shfl_down_sync(0xFFFFFFFFu, m, off);
    }
    int lane = tid & 31, warp = tid >> 5;
    if (lane == 0) {
        redf[warp][0] = ls0; redf[warp][1] = ls1;
        redf[warp][2] = ls2; redf[warp][3] = ls3;
        redf[warp][4] = bc;
        redm[warp] = m;
    }
    __syncthreads();
    if (tid == 0) {
        float tls[NS] = {0.f, 0.f, 0.f, 0.f};
        float tbc = 0.f;
        unsigned tm = (1u << NS) - 1u;
        for (int w = 0; w < 4; w++) {
#pragma unroll
            for (int s = 0; s < NS; s++) tls[s] += redf[w][s];
            tbc += redf[w][4];
            tm &= redm[w];
        }
        float cnt = (float)n;
#pragma unroll
        for (int s = 0; s < NS; s++) {
            out_loss[(size_t)s * n_edges + e] = tls[s] / cnt;
            out_mask[(size_t)s * n_edges + e] = ((tm >> s) & 1u) ? 1.f : 0.f;
        }
        out_black[e] = ((tbc / cnt) > 0.5f) ? 1.f : 0.f;
    }
}

// ---------------------------------------------------------------------------
extern "C" void kernel_launch(void* const* d_in, const int* in_sizes, int n_in,
                              void* d_out, int out_size)
{
    const float* start = (const float*)d_in[0];
    const float* end_p = (const float*)d_in[1];
    const float* imgs  = (const float*)d_in[2];
    const float* trans = (const float*)d_in[3];
    const float* K     = (const float*)d_in[4];
    const int*   npe   = (const int*)d_in[8];
    float* out = (float*)d_out;

    int n_edges = in_sizes[0] / 3;
    int P       = in_sizes[5];
    int num_src = in_sizes[3] / 12;  // 4
    long long hw = (long long)in_sizes[2] / (num_src + 1);
    int W = (int)(sqrt((double)hw) + 0.5);
    int H = (int)(hw / W);

    float* out_loss  = out;
    float* out_mask  = out_loss + (size_t)num_src * n_edges;
    float* out_black = out_mask + (size_t)num_src * n_edges;
    float* out_p2d1  = out_black + n_edges;
    float* out_p2d2  = out_p2d1 + 2 * (size_t)P;

    int prep_blocks = 1 + (n_edges + 255) / 256;
    prep_kernel<<<prep_blocks, 256>>>(npe, start, end_p, K, trans,
                                      n_edges, num_src, 10.0f / (float)W);
    point_kernel<<<n_edges, 128>>>(imgs, npe,
                                   out_loss, out_mask, out_black,
                                   out_p2d1, out_p2d2,
                                   W, H, n_edges, P);
}

// round 6
// speedup vs baseline: 1.3188x; 1.3188x over previous
#include <cuda_runtime.h>
#include <math.h>

// ---------------------------------------------------------------------------
// Multi-view edge photometric loss.
// Output f32: loss(S,N) | mask(S,N) | black(N) | p2d1(P,2) | p2d2(S,P,2)
// ---------------------------------------------------------------------------

#define MAXE 6144
#define NS 4
#define NHV2 20

__device__ float g_params[5 * MAXE * 8];
__device__ int   g_begin[MAXE];

// ---------------- fused prep: block 0 scans, others do edge params ---------
__device__ __forceinline__ void store_prm(int cam, int e, int nE,
                                          float p0x, float p0y,
                                          float dx, float dy, float upscale)
{
    float cx = dy, cy = -dx;
    float nrm = sqrtf(cx * cx + cy * cy);
    float sc = upscale / (nrm + 1e-6f);
    float* p = &g_params[((size_t)cam * nE + e) * 8];
    p[0] = p0x; p[1] = p0y; p[2] = dx; p[3] = dy; p[4] = cx * sc; p[5] = cy * sc;
}

__global__ void prep_kernel(const int* __restrict__ npe,
                            const float* __restrict__ sp,
                            const float* __restrict__ ep,
                            const float* __restrict__ K,
                            const float* __restrict__ trans,
                            int n_edges, int num_src, float upscale)
{
    if (blockIdx.x == 0) {
        __shared__ int ssum[256];
        int tid = threadIdx.x;
        int chunk = (n_edges + 255) / 256;
        int lo = min(tid * chunk, n_edges);
        int hi = min(lo + chunk, n_edges);
        int local = 0;
        for (int i = lo; i < hi; i++) local += npe[i];
        ssum[tid] = local;
        __syncthreads();
        for (int d = 1; d < 256; d <<= 1) {
            int t = (tid >= d) ? ssum[tid - d] : 0;
            __syncthreads();
            ssum[tid] += t;
            __syncthreads();
        }
        int run = ssum[tid] - local;
        for (int i = lo; i < hi; i++) { g_begin[i] = run; run += npe[i]; }
        return;
    }
    int e = (blockIdx.x - 1) * blockDim.x + threadIdx.x;
    if (e >= n_edges) return;
    float sx = sp[3 * e], sy = sp[3 * e + 1], sz = sp[3 * e + 2];
    float tx = ep[3 * e], ty = ep[3 * e + 1], tz = ep[3 * e + 2];
    {
        float pzs = K[6] * sx + K[7] * sy + K[8] * sz;
        float us  = (K[0] * sx + K[1] * sy + K[2] * sz) / (pzs + 1e-6f);
        float vs  = (K[3] * sx + K[4] * sy + K[5] * sz) / (pzs + 1e-6f);
        float pzt = K[6] * tx + K[7] * ty + K[8] * tz;
        float ut  = (K[0] * tx + K[1] * ty + K[2] * tz) / (pzt + 1e-6f);
        float vt  = (K[3] * tx + K[4] * ty + K[5] * tz) / (pzt + 1e-6f);
        store_prm(0, e, n_edges, us, vs, ut - us, vt - vs, upscale);
    }
    for (int s = 0; s < num_src; s++) {
        const float* T = trans + 12 * s;
        float pzs = T[8] * sx + T[9] * sy + T[10] * sz + T[11];
        float us  = (T[0] * sx + T[1] * sy + T[2] * sz + T[3]) / (pzs + 1e-6f);
        float vs  = (T[4] * sx + T[5] * sy + T[6] * sz + T[7]) / (pzs + 1e-6f);
        float pzt = T[8] * tx + T[9] * ty + T[10] * tz + T[11];
        float ut  = (T[0] * tx + T[1] * ty + T[2] * tz + T[3]) / (pzt + 1e-6f);
        float vt  = (T[4] * tx + T[5] * ty + T[6] * tz + T[7]) / (pzt + 1e-6f);
        store_prm(1 + s, e, n_edges, us, vs, ut - us, vt - vs, upscale);
    }
}

// --------------------------- bilinear sample (int offsets) -----------------
__device__ __forceinline__ float bilerp(const float* __restrict__ img,
                                        float u, float v, int W, int H)
{
    float x = u * (float)W - 0.5f;
    float y = v * (float)H - 0.5f;
    float x0f = floorf(x), y0f = floorf(y);
    float wx = x - x0f, wy = y - y0f;
    int x0i = min(max((int)x0f, 0), W - 1);
    int x1i = min(x0i + 1, W - 1);
    int y0i = min(max((int)y0f, 0), H - 1);
    int y1i = min(y0i + 1, H - 1);
    int r0 = y0i * W;
    int r1 = y1i * W;
    float v00 = __ldg(img + (r0 + x0i)), v01 = __ldg(img + (r0 + x1i));
    float v10 = __ldg(img + (r1 + x0i)), v11 = __ldg(img + (r1 + x1i));
    float top = fmaf(wx, v01 - v00, v00);
    float bot = fmaf(wx, v11 - v10, v10);
    return fmaf(wy, bot - top, top);
}

// ----------- point kernel: block/edge, 128 thr, 2 points/thread ------------
__global__ void __launch_bounds__(128, 9)
point_kernel(const float* __restrict__ imgs,
             const int* __restrict__ npe,
             float* __restrict__ out_loss, float* __restrict__ out_mask,
             float* __restrict__ out_black,
             float* __restrict__ out_p2d1, float* __restrict__ out_p2d2,
             int W, int H, int n_edges, int P)
{
    int e = blockIdx.x;
    int tid = threadIdx.x;

    __shared__ float sprm[30];     // 5 cams x 6 params, block-uniform
    __shared__ float redf[4][5];
    __shared__ unsigned redm[4];

    if (tid < 30) {
        int cam = tid / 6, j = tid - cam * 6;
        sprm[tid] = g_params[((size_t)cam * n_edges + e) * 8 + j];
    }
    __syncthreads();

    int b = g_begin[e];
    int n = npe[e];
    float inv_nh1 = 1.0f / (float)(n / NHV2 - 1);
    const int imgHW = W * H;

    float ls0 = 0.f, ls1 = 0.f, ls2 = 0.f, ls3 = 0.f;
    float bc = 0.f;
    unsigned m = (1u << NS) - 1u;

    float4* o1 = reinterpret_cast<float4*>(out_p2d1) + (b >> 1);
    float4* o2 = reinterpret_cast<float4*>(out_p2d2) + (b >> 1);
    const int strideP = P >> 1;   // float4 stride per source cam (fits int32)

    int npair = n >> 1;  // n multiple of 20
    for (int r = tid; r < npair; r += 128) {
        int h  = r / 10;
        int jj = r - h * 10;
        float cx = (float)h * inv_nh1;
        float base = (float)(2 * jj + ((jj < 5) ? -9 : -10));
        float cy0 = base * (1.0f / 9.0f);
        float cy1 = (base + 1.0f) * (1.0f / 9.0f);

        // reference camera (params via broadcast LDS)
        float u0 = fmaf(sprm[2], cx, fmaf(sprm[4], cy0, sprm[0]));
        float v0 = fmaf(sprm[3], cx, fmaf(sprm[5], cy0, sprm[1]));
        float u1 = fmaf(sprm[2], cx, fmaf(sprm[4], cy1, sprm[0]));
        float v1 = fmaf(sprm[3], cx, fmaf(sprm[5], cy1, sprm[1]));
        bool vm1a = (u0 > 0.f) & (u0 < 1.f) & (v0 > 0.f) & (v0 < 1.f);
        bool vm1b = (u1 > 0.f) & (u1 < 1.f) & (v1 > 0.f) & (v1 < 1.f);
        u0 = fminf(fmaxf(u0, 0.f), 0.999999f);
        v0 = fminf(fmaxf(v0, 0.f), 0.999999f);
        u1 = fminf(fmaxf(u1, 0.f), 0.999999f);
        v1 = fminf(fmaxf(v1, 0.f), 0.999999f);
        o1[r] = make_float4(u0, v0, u1, v1);
        float s1a = bilerp(imgs, u0, v0, W, H);
        float s1b = bilerp(imgs, u1, v1, W, H);
        if (s1a < 0.01f) bc += 1.f;
        if (s1b < 0.01f) bc += 1.f;

#pragma unroll
        for (int s = 0; s < NS; s++) {
            const float* q = &sprm[(s + 1) * 6];
            float ua = fmaf(q[2], cx, fmaf(q[4], cy0, q[0]));
            float va = fmaf(q[3], cx, fmaf(q[5], cy0, q[1]));
            float ub = fmaf(q[2], cx, fmaf(q[4], cy1, q[0]));
            float vb = fmaf(q[3], cx, fmaf(q[5], cy1, q[1]));
            bool oka = vm1a & (ua > 0.f) & (ua < 1.f) & (va > 0.f) & (va < 1.f);
            bool okb = vm1b & (ub > 0.f) & (ub < 1.f) & (vb > 0.f) & (vb < 1.f);
            ua = fminf(fmaxf(ua, 0.f), 0.999999f);
            va = fminf(fmaxf(va, 0.f), 0.999999f);
            ub = fminf(fmaxf(ub, 0.f), 0.999999f);
            vb = fminf(fmaxf(vb, 0.f), 0.999999f);
            o2[s * strideP + r] = make_float4(ua, va, ub, vb);
            const float* img = imgs + (s + 1) * imgHW;
            float s2a = bilerp(img, ua, va, W, H);
            float s2b = bilerp(img, ub, vb, W, H);
            float da = s2a - s1a;
            float db = s2b - s1b;
            float acc = fmaf(da, da, db * db);
            if (s == 0) ls0 += acc;
            else if (s == 1) ls1 += acc;
            else if (s == 2) ls2 += acc;
            else ls3 += acc;
            if (!(oka && okb)) m &= ~(1u << s);
        }
    }

    // warp + block reduce
#pragma unroll
    for (int off = 16; off > 0; off >>= 1) {
        ls0 += __shfl_down_sync(0xFFFFFFFFu, ls0, off);
        ls1 += __shfl_down_sync(0xFFFFFFFFu, ls1, off);
        ls2 += __shfl_down_sync(0xFFFFFFFFu, ls2, off);
        ls3 += __shfl_down_sync(0xFFFFFFFFu, ls3, off);
        bc  += __shfl_down_sync(0xFFFFFFFFu, bc, off);
        m   &= __shfl_down_sync(0xFFFFFFFFu, m, off);
    }
    int lane = tid & 31, warp = tid >> 5;
    if (lane == 0) {
        redf[warp][0] = ls0; redf[warp][1] = ls1;
        redf[warp][2] = ls2; redf[warp][3] = ls3;
        redf[warp][4] = bc;
        redm[warp] = m;
    }
    __syncthreads();
    if (tid == 0) {
        float tls[NS] = {0.f, 0.f, 0.f, 0.f};
        float tbc = 0.f;
        unsigned tm = (1u << NS) - 1u;
        for (int w = 0; w < 4; w++) {
#pragma unroll
            for (int s = 0; s < NS; s++) tls[s] += redf[w][s];
            tbc += redf[w][4];
            tm &= redm[w];
        }
        float cnt = (float)n;
#pragma unroll
        for (int s = 0; s < NS; s++) {
            out_loss[s * n_edges + e] = tls[s] / cnt;
            out_mask[s * n_edges + e] = ((tm >> s) & 1u) ? 1.f : 0.f;
        }
        out_black[e] = ((tbc / cnt) > 0.5f) ? 1.f : 0.f;
    }
}

// ---------------------------------------------------------------------------
extern "C" void kernel_launch(void* const* d_in, const int* in_sizes, int n_in,
                              void* d_out, int out_size)
{
    const float* start = (const float*)d_in[0];
    const float* end_p = (const float*)d_in[1];
    const float* imgs  = (const float*)d_in[2];
    const float* trans = (const float*)d_in[3];
    const float* K     = (const float*)d_in[4];
    const int*   npe   = (const int*)d_in[8];
    float* out = (float*)d_out;

    int n_edges = in_sizes[0] / 3;
    int P       = in_sizes[5];
    int num_src = in_sizes[3] / 12;  // 4
    long long hw = (long long)in_sizes[2] / (num_src + 1);
    int W = (int)(sqrt((double)hw) + 0.5);
    int H = (int)(hw / W);

    float* out_loss  = out;
    float* out_mask  = out_loss + (size_t)num_src * n_edges;
    float* out_black = out_mask + (size_t)num_src * n_edges;
    float* out_p2d1  = out_black + n_edges;
    float* out_p2d2  = out_p2d1 + 2 * (size_t)P;

    int prep_blocks = 1 + (n_edges + 255) / 256;
    prep_kernel<<<prep_blocks, 256>>>(npe, start, end_p, K, trans,
                                      n_edges, num_src, 10.0f / (float)W);
    point_kernel<<<n_edges, 128>>>(imgs, npe,
                                   out_loss, out_mask, out_black,
                                   out_p2d1, out_p2d2,
                                   W, H, n_edges, P);
}

// round 7
// speedup vs baseline: 1.5576x; 1.1810x over previous
#include <cuda_runtime.h>
#include <math.h>

// ---------------------------------------------------------------------------
// Multi-view edge photometric loss.
// Output f32: loss(S,N) | mask(S,N) | black(N) | p2d1(P,2) | p2d2(S,P,2)
// Images are re-tiled per call into a 4-row interleaved layout so that the 4
// bilinear corners of a sample share one 128B sector.
// ---------------------------------------------------------------------------

#define MAXE 6144
#define NS 4
#define NHV2 20
#define TIMG_CAP (4 * 1024 * 1024)   // floats (16 MB) — 5 x 800 x 800 fits

__device__ float g_params[5 * MAXE * 8];
__device__ int   g_begin[MAXE];
__device__ float g_timg[TIMG_CAP];

// ---------------- fused prep: block 0 scans, others do edge params ---------
__device__ __forceinline__ void store_prm(int cam, int e, int nE,
                                          float p0x, float p0y,
                                          float dx, float dy, float upscale)
{
    float cx = dy, cy = -dx;
    float nrm = sqrtf(cx * cx + cy * cy);
    float sc = upscale / (nrm + 1e-6f);
    float* p = &g_params[((size_t)cam * nE + e) * 8];
    p[0] = p0x; p[1] = p0y; p[2] = dx; p[3] = dy; p[4] = cx * sc; p[5] = cy * sc;
}

__global__ void prep_kernel(const int* __restrict__ npe,
                            const float* __restrict__ sp,
                            const float* __restrict__ ep,
                            const float* __restrict__ K,
                            const float* __restrict__ trans,
                            int n_edges, int num_src, float upscale)
{
    if (blockIdx.x == 0) {
        __shared__ int ssum[256];
        int tid = threadIdx.x;
        int chunk = (n_edges + 255) / 256;
        int lo = min(tid * chunk, n_edges);
        int hi = min(lo + chunk, n_edges);
        int local = 0;
        for (int i = lo; i < hi; i++) local += npe[i];
        ssum[tid] = local;
        __syncthreads();
        for (int d = 1; d < 256; d <<= 1) {
            int t = (tid >= d) ? ssum[tid - d] : 0;
            __syncthreads();
            ssum[tid] += t;
            __syncthreads();
        }
        int run = ssum[tid] - local;
        for (int i = lo; i < hi; i++) { g_begin[i] = run; run += npe[i]; }
        return;
    }
    int e = (blockIdx.x - 1) * blockDim.x + threadIdx.x;
    if (e >= n_edges) return;
    float sx = sp[3 * e], sy = sp[3 * e + 1], sz = sp[3 * e + 2];
    float tx = ep[3 * e], ty = ep[3 * e + 1], tz = ep[3 * e + 2];
    {
        float pzs = K[6] * sx + K[7] * sy + K[8] * sz;
        float us  = (K[0] * sx + K[1] * sy + K[2] * sz) / (pzs + 1e-6f);
        float vs  = (K[3] * sx + K[4] * sy + K[5] * sz) / (pzs + 1e-6f);
        float pzt = K[6] * tx + K[7] * ty + K[8] * tz;
        float ut  = (K[0] * tx + K[1] * ty + K[2] * tz) / (pzt + 1e-6f);
        float vt  = (K[3] * tx + K[4] * ty + K[5] * tz) / (pzt + 1e-6f);
        store_prm(0, e, n_edges, us, vs, ut - us, vt - vs, upscale);
    }
    for (int s = 0; s < num_src; s++) {
        const float* T = trans + 12 * s;
        float pzs = T[8] * sx + T[9] * sy + T[10] * sz + T[11];
        float us  = (T[0] * sx + T[1] * sy + T[2] * sz + T[3]) / (pzs + 1e-6f);
        float vs  = (T[4] * sx + T[5] * sy + T[6] * sz + T[7]) / (pzs + 1e-6f);
        float pzt = T[8] * tx + T[9] * ty + T[10] * tz + T[11];
        float ut  = (T[0] * tx + T[1] * ty + T[2] * tz + T[3]) / (pzt + 1e-6f);
        float vt  = (T[4] * tx + T[5] * ty + T[6] * tz + T[7]) / (pzt + 1e-6f);
        store_prm(1 + s, e, n_edges, us, vs, ut - us, vt - vs, upscale);
    }
}

// ---------------- tile pass: row-major -> 4-row interleaved ----------------
// tiled idx(x,y) = ((y>>2)*W + x)*4 + (y&3); per-image stride = G*4*W, G=ceil(H/4)
__global__ void tile_kernel(const float* __restrict__ imgs,
                            int W, int H, int nimg)
{
    int G = (H + 3) >> 2;
    int per = G * W;                    // float4 slots per image
    int total = nimg * per;
    int idx = blockIdx.x * blockDim.x + threadIdx.x;
    if (idx >= total) return;
    int c = idx / per;
    int rem = idx - c * per;
    int g = rem / W;
    int x = rem - g * W;
    const float* img = imgs + (size_t)c * W * H;
    float4 v;
    int y0 = g * 4;
    v.x = img[(size_t)y0 * W + x];
    v.y = (y0 + 1 < H) ? img[(size_t)(y0 + 1) * W + x] : 0.f;
    v.z = (y0 + 2 < H) ? img[(size_t)(y0 + 2) * W + x] : 0.f;
    v.w = (y0 + 3 < H) ? img[(size_t)(y0 + 3) * W + x] : 0.f;
    reinterpret_cast<float4*>(g_timg)[(size_t)c * per + rem] = v;
}

// ------------------- bilinear sample on tiled layout -----------------------
__device__ __forceinline__ float bilerp_t(const float* __restrict__ timg,
                                          float u, float v, int W, int H)
{
    float x = u * (float)W - 0.5f;
    float y = v * (float)H - 0.5f;
    float x0f = floorf(x), y0f = floorf(y);
    float wx = x - x0f, wy = y - y0f;
    int x0 = min(max((int)x0f, 0), W - 1);
    int x1 = min(x0 + 1, W - 1);
    int y0 = min(max((int)y0f, 0), H - 1);
    int y1 = min(y0 + 1, H - 1);
    int t0 = (y0 >> 2) * W, w0 = y0 & 3;
    int t1 = (y1 >> 2) * W, w1 = y1 & 3;
    float v00 = __ldg(timg + (((t0 + x0) << 2) | w0));
    float v01 = __ldg(timg + (((t0 + x1) << 2) | w0));
    float v10 = __ldg(timg + (((t1 + x0) << 2) | w1));
    float v11 = __ldg(timg + (((t1 + x1) << 2) | w1));
    float top = fmaf(wx, v01 - v00, v00);
    float bot = fmaf(wx, v11 - v10, v10);
    return fmaf(wy, bot - top, top);
}

// ----------- point kernel: block/edge, 128 thr, 2 points/thread ------------
__global__ void __launch_bounds__(128, 9)
point_kernel(const int* __restrict__ npe,
             float* __restrict__ out_loss, float* __restrict__ out_mask,
             float* __restrict__ out_black,
             float* __restrict__ out_p2d1, float* __restrict__ out_p2d2,
             int W, int H, int n_edges, int P)
{
    int e = blockIdx.x;
    int tid = threadIdx.x;

    __shared__ float sprm[30];     // 5 cams x 6 params, block-uniform
    __shared__ float redf[4][5];
    __shared__ unsigned redm[4];

    if (tid < 30) {
        int cam = tid / 6, j = tid - cam * 6;
        sprm[tid] = g_params[((size_t)cam * n_edges + e) * 8 + j];
    }
    __syncthreads();

    int b = g_begin[e];
    int n = npe[e];
    float inv_nh1 = 1.0f / (float)(n / NHV2 - 1);
    const int tstride = ((H + 3) >> 2) * 4 * W;   // tiled image stride (floats)

    float ls0 = 0.f, ls1 = 0.f, ls2 = 0.f, ls3 = 0.f;
    float bc = 0.f;
    unsigned m = (1u << NS) - 1u;

    float4* o1 = reinterpret_cast<float4*>(out_p2d1) + (b >> 1);
    float4* o2 = reinterpret_cast<float4*>(out_p2d2) + (b >> 1);
    const int strideP = P >> 1;

    int npair = n >> 1;  // n multiple of 20
    for (int r = tid; r < npair; r += 128) {
        int h  = r / 10;
        int jj = r - h * 10;
        float cx = (float)h * inv_nh1;
        float base = (float)(2 * jj + ((jj < 5) ? -9 : -10));
        float cy0 = base * (1.0f / 9.0f);
        float cy1 = (base + 1.0f) * (1.0f / 9.0f);

        // reference camera (params via broadcast LDS)
        float u0 = fmaf(sprm[2], cx, fmaf(sprm[4], cy0, sprm[0]));
        float v0 = fmaf(sprm[3], cx, fmaf(sprm[5], cy0, sprm[1]));
        float u1 = fmaf(sprm[2], cx, fmaf(sprm[4], cy1, sprm[0]));
        float v1 = fmaf(sprm[3], cx, fmaf(sprm[5], cy1, sprm[1]));
        bool vm1a = (u0 > 0.f) & (u0 < 1.f) & (v0 > 0.f) & (v0 < 1.f);
        bool vm1b = (u1 > 0.f) & (u1 < 1.f) & (v1 > 0.f) & (v1 < 1.f);
        u0 = fminf(fmaxf(u0, 0.f), 0.999999f);
        v0 = fminf(fmaxf(v0, 0.f), 0.999999f);
        u1 = fminf(fmaxf(u1, 0.f), 0.999999f);
        v1 = fminf(fmaxf(v1, 0.f), 0.999999f);
        o1[r] = make_float4(u0, v0, u1, v1);
        float s1a = bilerp_t(g_timg, u0, v0, W, H);
        float s1b = bilerp_t(g_timg, u1, v1, W, H);
        if (s1a < 0.01f) bc += 1.f;
        if (s1b < 0.01f) bc += 1.f;

#pragma unroll
        for (int s = 0; s < NS; s++) {
            const float* q = &sprm[(s + 1) * 6];
            float ua = fmaf(q[2], cx, fmaf(q[4], cy0, q[0]));
            float va = fmaf(q[3], cx, fmaf(q[5], cy0, q[1]));
            float ub = fmaf(q[2], cx, fmaf(q[4], cy1, q[0]));
            float vb = fmaf(q[3], cx, fmaf(q[5], cy1, q[1]));
            bool oka = vm1a & (ua > 0.f) & (ua < 1.f) & (va > 0.f) & (va < 1.f);
            bool okb = vm1b & (ub > 0.f) & (ub < 1.f) & (vb > 0.f) & (vb < 1.f);
            ua = fminf(fmaxf(ua, 0.f), 0.999999f);
            va = fminf(fmaxf(va, 0.f), 0.999999f);
            ub = fminf(fmaxf(ub, 0.f), 0.999999f);
            vb = fminf(fmaxf(vb, 0.f), 0.999999f);
            o2[s * strideP + r] = make_float4(ua, va, ub, vb);
            const float* img = g_timg + (s + 1) * tstride;
            float s2a = bilerp_t(img, ua, va, W, H);
            float s2b = bilerp_t(img, ub, vb, W, H);
            float da = s2a - s1a;
            float db = s2b - s1b;
            float acc = fmaf(da, da, db * db);
            if (s == 0) ls0 += acc;
            else if (s == 1) ls1 += acc;
            else if (s == 2) ls2 += acc;
            else ls3 += acc;
            if (!(oka && okb)) m &= ~(1u << s);
        }
    }

    // warp + block reduce
#pragma unroll
    for (int off = 16; off > 0; off >>= 1) {
        ls0 += __shfl_down_sync(0xFFFFFFFFu, ls0, off);
        ls1 += __shfl_down_sync(0xFFFFFFFFu, ls1, off);
        ls2 += __shfl_down_sync(0xFFFFFFFFu, ls2, off);
        ls3 += __shfl_down_sync(0xFFFFFFFFu, ls3, off);
        bc  += __shfl_down_sync(0xFFFFFFFFu, bc, off);
        m   &= __shfl_down_sync(0xFFFFFFFFu, m, off);
    }
    int lane = tid & 31, warp = tid >> 5;
    if (lane == 0) {
        redf[warp][0] = ls0; redf[warp][1] = ls1;
        redf[warp][2] = ls2; redf[warp][3] = ls3;
        redf[warp][4] = bc;
        redm[warp] = m;
    }
    __syncthreads();
    if (tid == 0) {
        float tls[NS] = {0.f, 0.f, 0.f, 0.f};
        float tbc = 0.f;
        unsigned tm = (1u << NS) - 1u;
        for (int w = 0; w < 4; w++) {
#pragma unroll
            for (int s = 0; s < NS; s++) tls[s] += redf[w][s];
            tbc += redf[w][4];
            tm &= redm[w];
        }
        float cnt = (float)n;
#pragma unroll
        for (int s = 0; s < NS; s++) {
            out_loss[s * n_edges + e] = tls[s] / cnt;
            out_mask[s * n_edges + e] = ((tm >> s) & 1u) ? 1.f : 0.f;
        }
        out_black[e] = ((tbc / cnt) > 0.5f) ? 1.f : 0.f;
    }
}

// ---------------------------------------------------------------------------
extern "C" void kernel_launch(void* const* d_in, const int* in_sizes, int n_in,
                              void* d_out, int out_size)
{
    const float* start = (const float*)d_in[0];
    const float* end_p = (const float*)d_in[1];
    const float* imgs  = (const float*)d_in[2];
    const float* trans = (const float*)d_in[3];
    const float* K     = (const float*)d_in[4];
    const int*   npe   = (const int*)d_in[8];
    float* out = (float*)d_out;

    int n_edges = in_sizes[0] / 3;
    int P       = in_sizes[5];
    int num_src = in_sizes[3] / 12;  // 4
    int nimg    = num_src + 1;
    long long hw = (long long)in_sizes[2] / nimg;
    int W = (int)(sqrt((double)hw) + 0.5);
    int H = (int)(hw / W);

    float* out_loss  = out;
    float* out_mask  = out_loss + (size_t)num_src * n_edges;
    float* out_black = out_mask + (size_t)num_src * n_edges;
    float* out_p2d1  = out_black + n_edges;
    float* out_p2d2  = out_p2d1 + 2 * (size_t)P;

    int prep_blocks = 1 + (n_edges + 255) / 256;
    prep_kernel<<<prep_blocks, 256>>>(npe, start, end_p, K, trans,
                                      n_edges, num_src, 10.0f / (float)W);
    int G = (H + 3) >> 2;
    int tile_total = nimg * G * W;
    tile_kernel<<<(tile_total + 255) / 256, 256>>>(imgs, W, H, nimg);
    point_kernel<<<n_edges, 128>>>(npe,
                                   out_loss, out_mask, out_black,
                                   out_p2d1, out_p2d2,
                                   W, H, n_edges, P);
}

// round 8
// speedup vs baseline: 1.6256x; 1.0437x over previous
#include <cuda_runtime.h>
#include <math.h>

// ---------------------------------------------------------------------------
// Multi-view edge photometric loss.
// Output f32: loss(S,N) | mask(S,N) | black(N) | p2d1(P,2) | p2d2(S,P,2)
// Images re-tiled (4-row interleave) so a bilinear's 4 corners share sectors.
// prep (scan + edge params) and tile fused into one launch (disjoint data).
// ---------------------------------------------------------------------------

#define MAXE 6144
#define NS 4
#define NHV2 20
#define TIMG_CAP (4 * 1024 * 1024)   // floats (16 MB) — 5 x 800 x 800 fits

__device__ float g_params[5 * MAXE * 8];
__device__ int   g_begin[MAXE];
__device__ float g_timg[TIMG_CAP];

// ---------------- fused prep+tile: block-range dispatch --------------------
__device__ __forceinline__ void store_prm(int cam, int e, int nE,
                                          float p0x, float p0y,
                                          float dx, float dy, float upscale)
{
    float cx = dy, cy = -dx;
    float nrm = sqrtf(cx * cx + cy * cy);
    float sc = upscale / (nrm + 1e-6f);
    float* p = &g_params[((size_t)cam * nE + e) * 8];
    p[0] = p0x; p[1] = p0y; p[2] = dx; p[3] = dy; p[4] = cx * sc; p[5] = cy * sc;
}

__global__ void prep_tile_kernel(const int* __restrict__ npe,
                                 const float* __restrict__ sp,
                                 const float* __restrict__ ep,
                                 const float* __restrict__ K,
                                 const float* __restrict__ trans,
                                 const float* __restrict__ imgs,
                                 int n_edges, int num_src, float upscale,
                                 int W, int H, int param_blocks)
{
    int blk = blockIdx.x;
    if (blk == 0) {
        // block-wide exclusive scan of npe into g_begin
        __shared__ int ssum[256];
        int tid = threadIdx.x;
        int chunk = (n_edges + 255) / 256;
        int lo = min(tid * chunk, n_edges);
        int hi = min(lo + chunk, n_edges);
        int local = 0;
        for (int i = lo; i < hi; i++) local += npe[i];
        ssum[tid] = local;
        __syncthreads();
        for (int d = 1; d < 256; d <<= 1) {
            int t = (tid >= d) ? ssum[tid - d] : 0;
            __syncthreads();
            ssum[tid] += t;
            __syncthreads();
        }
        int run = ssum[tid] - local;
        for (int i = lo; i < hi; i++) { g_begin[i] = run; run += npe[i]; }
        return;
    }
    if (blk <= param_blocks) {
        int e = (blk - 1) * blockDim.x + threadIdx.x;
        if (e >= n_edges) return;
        float sx = sp[3 * e], sy = sp[3 * e + 1], sz = sp[3 * e + 2];
        float tx = ep[3 * e], ty = ep[3 * e + 1], tz = ep[3 * e + 2];
        {
            float pzs = K[6] * sx + K[7] * sy + K[8] * sz;
            float us  = (K[0] * sx + K[1] * sy + K[2] * sz) / (pzs + 1e-6f);
            float vs  = (K[3] * sx + K[4] * sy + K[5] * sz) / (pzs + 1e-6f);
            float pzt = K[6] * tx + K[7] * ty + K[8] * tz;
            float ut  = (K[0] * tx + K[1] * ty + K[2] * tz) / (pzt + 1e-6f);
            float vt  = (K[3] * tx + K[4] * ty + K[5] * tz) / (pzt + 1e-6f);
            store_prm(0, e, n_edges, us, vs, ut - us, vt - vs, upscale);
        }
        for (int s = 0; s < num_src; s++) {
            const float* T = trans + 12 * s;
            float pzs = T[8] * sx + T[9] * sy + T[10] * sz + T[11];
            float us  = (T[0] * sx + T[1] * sy + T[2] * sz + T[3]) / (pzs + 1e-6f);
            float vs  = (T[4] * sx + T[5] * sy + T[6] * sz + T[7]) / (pzs + 1e-6f);
            float pzt = T[8] * tx + T[9] * ty + T[10] * tz + T[11];
            float ut  = (T[0] * tx + T[1] * ty + T[2] * tz + T[3]) / (pzt + 1e-6f);
            float vt  = (T[4] * tx + T[5] * ty + T[6] * tz + T[7]) / (pzt + 1e-6f);
            store_prm(1 + s, e, n_edges, us, vs, ut - us, vt - vs, upscale);
        }
        return;
    }
    // tile pass: row-major -> 4-row interleaved
    int G = (H + 3) >> 2;
    int per = G * W;                      // float4 slots per image
    int nimg = num_src + 1;
    int total = nimg * per;
    int idx = (blk - 1 - param_blocks) * blockDim.x + threadIdx.x;
    if (idx >= total) return;
    int c = idx / per;
    int rem = idx - c * per;
    int g = rem / W;
    int x = rem - g * W;
    const float* img = imgs + (size_t)c * W * H;
    float4 v;
    int y0 = g * 4;
    v.x = img[(size_t)y0 * W + x];
    v.y = (y0 + 1 < H) ? img[(size_t)(y0 + 1) * W + x] : 0.f;
    v.z = (y0 + 2 < H) ? img[(size_t)(y0 + 2) * W + x] : 0.f;
    v.w = (y0 + 3 < H) ? img[(size_t)(y0 + 3) * W + x] : 0.f;
    reinterpret_cast<float4*>(g_timg)[(size_t)c * per + rem] = v;
}

// ------------------- bilinear sample on tiled layout -----------------------
__device__ __forceinline__ float bilerp_t(const float* __restrict__ timg,
                                          float u, float v, int W, int H)
{
    float x = u * (float)W - 0.5f;
    float y = v * (float)H - 0.5f;
    float x0f = floorf(x), y0f = floorf(y);
    float wx = x - x0f, wy = y - y0f;
    int x0 = min(max((int)x0f, 0), W - 1);
    int x1 = min(x0 + 1, W - 1);
    int y0 = min(max((int)y0f, 0), H - 1);
    int y1 = min(y0 + 1, H - 1);
    int t0 = (y0 >> 2) * W, w0 = y0 & 3;
    int t1 = (y1 >> 2) * W, w1 = y1 & 3;
    float v00 = __ldg(timg + (((t0 + x0) << 2) | w0));
    float v01 = __ldg(timg + (((t0 + x1) << 2) | w0));
    float v10 = __ldg(timg + (((t1 + x0) << 2) | w1));
    float v11 = __ldg(timg + (((t1 + x1) << 2) | w1));
    float top = fmaf(wx, v01 - v00, v00);
    float bot = fmaf(wx, v11 - v10, v10);
    return fmaf(wy, bot - top, top);
}

// ----------- point kernel: block/edge, 128 thr, 2 points/thread ------------
__global__ void __launch_bounds__(128, 9)
point_kernel(const int* __restrict__ npe,
             float* __restrict__ out_loss, float* __restrict__ out_mask,
             float* __restrict__ out_black,
             float* __restrict__ out_p2d1, float* __restrict__ out_p2d2,
             int W, int H, int n_edges, int P)
{
    int e = blockIdx.x;
    int tid = threadIdx.x;

    __shared__ float sprm[30];
    __shared__ float redf[4][5];
    __shared__ unsigned redm[4];

    if (tid < 30) {
        int cam = tid / 6, j = tid - cam * 6;
        sprm[tid] = g_params[((size_t)cam * n_edges + e) * 8 + j];
    }
    __syncthreads();

    int b = g_begin[e];
    int n = npe[e];
    float inv_nh1 = 1.0f / (float)(n / NHV2 - 1);
    const int tstride = ((H + 3) >> 2) * 4 * W;

    float ls0 = 0.f, ls1 = 0.f, ls2 = 0.f, ls3 = 0.f;
    float bc = 0.f;
    unsigned m = (1u << NS) - 1u;

    float4* o1 = reinterpret_cast<float4*>(out_p2d1) + (b >> 1);
    float4* o2 = reinterpret_cast<float4*>(out_p2d2) + (b >> 1);
    const int strideP = P >> 1;

    int npair = n >> 1;
    // incremental (h, jj) tracking: r = h*10 + jj, r advances by 128
    int h  = tid / 10;
    int jj = tid - h * 10;
    for (int r = tid; r < npair; r += 128) {
        float cx = (float)h * inv_nh1;
        float base = (float)(2 * jj + ((jj < 5) ? -9 : -10));
        float cy0 = base * (1.0f / 9.0f);
        float cy1 = (base + 1.0f) * (1.0f / 9.0f);

        float u0 = fmaf(sprm[2], cx, fmaf(sprm[4], cy0, sprm[0]));
        float v0 = fmaf(sprm[3], cx, fmaf(sprm[5], cy0, sprm[1]));
        float u1 = fmaf(sprm[2], cx, fmaf(sprm[4], cy1, sprm[0]));
        float v1 = fmaf(sprm[3], cx, fmaf(sprm[5], cy1, sprm[1]));
        bool vm1a = (u0 > 0.f) & (u0 < 1.f) & (v0 > 0.f) & (v0 < 1.f);
        bool vm1b = (u1 > 0.f) & (u1 < 1.f) & (v1 > 0.f) & (v1 < 1.f);
        u0 = fminf(fmaxf(u0, 0.f), 0.999999f);
        v0 = fminf(fmaxf(v0, 0.f), 0.999999f);
        u1 = fminf(fmaxf(u1, 0.f), 0.999999f);
        v1 = fminf(fmaxf(v1, 0.f), 0.999999f);
        o1[r] = make_float4(u0, v0, u1, v1);
        float s1a = bilerp_t(g_timg, u0, v0, W, H);
        float s1b = bilerp_t(g_timg, u1, v1, W, H);
        if (s1a < 0.01f) bc += 1.f;
        if (s1b < 0.01f) bc += 1.f;

#pragma unroll
        for (int s = 0; s < NS; s++) {
            const float* q = &sprm[(s + 1) * 6];
            float ua = fmaf(q[2], cx, fmaf(q[4], cy0, q[0]));
            float va = fmaf(q[3], cx, fmaf(q[5], cy0, q[1]));
            float ub = fmaf(q[2], cx, fmaf(q[4], cy1, q[0]));
            float vb = fmaf(q[3], cx, fmaf(q[5], cy1, q[1]));
            bool oka = vm1a & (ua > 0.f) & (ua < 1.f) & (va > 0.f) & (va < 1.f);
            bool okb = vm1b & (ub > 0.f) & (ub < 1.f) & (vb > 0.f) & (vb < 1.f);
            ua = fminf(fmaxf(ua, 0.f), 0.999999f);
            va = fminf(fmaxf(va, 0.f), 0.999999f);
            ub = fminf(fmaxf(ub, 0.f), 0.999999f);
            vb = fminf(fmaxf(vb, 0.f), 0.999999f);
            o2[s * strideP + r] = make_float4(ua, va, ub, vb);
            const float* img = g_timg + (s + 1) * tstride;
            float s2a = bilerp_t(img, ua, va, W, H);
            float s2b = bilerp_t(img, ub, vb, W, H);
            float da = s2a - s1a;
            float db = s2b - s1b;
            float acc = fmaf(da, da, db * db);
            if (s == 0) ls0 += acc;
            else if (s == 1) ls1 += acc;
            else if (s == 2) ls2 += acc;
            else ls3 += acc;
            if (!(oka && okb)) m &= ~(1u << s);
        }

        // advance (h, jj) by 128 points-pairs: 128 = 12*10 + 8
        jj += 8;
        if (jj >= 10) { jj -= 10; h += 13; } else { h += 12; }
    }

    // warp + block reduce
#pragma unroll
    for (int off = 16; off > 0; off >>= 1) {
        ls0 += __shfl_down_sync(0xFFFFFFFFu, ls0, off);
        ls1 += __shfl_down_sync(0xFFFFFFFFu, ls1, off);
        ls2 += __shfl_down_sync(0xFFFFFFFFu, ls2, off);
        ls3 += __shfl_down_sync(0xFFFFFFFFu, ls3, off);
        bc  += __shfl_down_sync(0xFFFFFFFFu, bc, off);
        m   &= __shfl_down_sync(0xFFFFFFFFu, m, off);
    }
    int lane = tid & 31, warp = tid >> 5;
    if (lane == 0) {
        redf[warp][0] = ls0; redf[warp][1] = ls1;
        redf[warp][2] = ls2; redf[warp][3] = ls3;
        redf[warp][4] = bc;
        redm[warp] = m;
    }
    __syncthreads();
    if (tid == 0) {
        float tls[NS] = {0.f, 0.f, 0.f, 0.f};
        float tbc = 0.f;
        unsigned tm = (1u << NS) - 1u;
        for (int w = 0; w < 4; w++) {
#pragma unroll
            for (int s = 0; s < NS; s++) tls[s] += redf[w][s];
            tbc += redf[w][4];
            tm &= redm[w];
        }
        float cnt = (float)n;
#pragma unroll
        for (int s = 0; s < NS; s++) {
            out_loss[s * n_edges + e] = tls[s] / cnt;
            out_mask[s * n_edges + e] = ((tm >> s) & 1u) ? 1.f : 0.f;
        }
        out_black[e] = ((tbc / cnt) > 0.5f) ? 1.f : 0.f;
    }
}

// ---------------------------------------------------------------------------
extern "C" void kernel_launch(void* const* d_in, const int* in_sizes, int n_in,
                              void* d_out, int out_size)
{
    const float* start = (const float*)d_in[0];
    const float* end_p = (const float*)d_in[1];
    const float* imgs  = (const float*)d_in[2];
    const float* trans = (const float*)d_in[3];
    const float* K     = (const float*)d_in[4];
    const int*   npe   = (const int*)d_in[8];
    float* out = (float*)d_out;

    int n_edges = in_sizes[0] / 3;
    int P       = in_sizes[5];
    int num_src = in_sizes[3] / 12;  // 4
    int nimg    = num_src + 1;
    long long hw = (long long)in_sizes[2] / nimg;
    int W = (int)(sqrt((double)hw) + 0.5);
    int H = (int)(hw / W);

    float* out_loss  = out;
    float* out_mask  = out_loss + (size_t)num_src * n_edges;
    float* out_black = out_mask + (size_t)num_src * n_edges;
    float* out_p2d1  = out_black + n_edges;
    float* out_p2d2  = out_p2d1 + 2 * (size_t)P;

    int param_blocks = (n_edges + 255) / 256;
    int G = (H + 3) >> 2;
    int tile_total = nimg * G * W;
    int tile_blocks = (tile_total + 255) / 256;
    prep_tile_kernel<<<1 + param_blocks + tile_blocks, 256>>>(
        npe, start, end_p, K, trans, imgs,
        n_edges, num_src, 10.0f / (float)W, W, H, param_blocks);
    point_kernel<<<n_edges, 128>>>(npe,
                                   out_loss, out_mask, out_black,
                                   out_p2d1, out_p2d2,
                                   W, H, n_edges, P);
}

// round 9
// speedup vs baseline: 1.6579x; 1.0199x over previous
#include <cuda_runtime.h>
#include <math.h>

// ---------------------------------------------------------------------------
// Multi-view edge photometric loss.
// Output f32: loss(S,N) | mask(S,N) | black(N) | p2d1(P,2) | p2d2(S,P,2)
// Images re-tiled (4-row interleave) so a bilinear's 4 corners share sectors.
// prep (scan + edge params) and tile fused into one launch (disjoint data).
// ---------------------------------------------------------------------------

#define MAXE 6144
#define NS 4
#define NHV2 20
#define TIMG_CAP (4 * 1024 * 1024)   // floats (16 MB) — 5 x 800 x 800 fits

__device__ float4 g_params4[5 * MAXE * 2];   // per (cam,edge): 8 floats (6 used)
__device__ int    g_begin[MAXE];
__device__ float  g_timg[TIMG_CAP];

// ---------------- fused prep+tile: block-range dispatch --------------------
__device__ __forceinline__ void store_prm(int cam, int e, int nE,
                                          float p0x, float p0y,
                                          float dx, float dy, float upscale)
{
    float cx = dy, cy = -dx;
    float nrm = sqrtf(cx * cx + cy * cy);
    float sc = upscale / (nrm + 1e-6f);
    float* p = reinterpret_cast<float*>(&g_params4[((size_t)cam * nE + e) * 2]);
    p[0] = p0x; p[1] = p0y; p[2] = dx; p[3] = dy; p[4] = cx * sc; p[5] = cy * sc;
}

__global__ void prep_tile_kernel(const int* __restrict__ npe,
                                 const float* __restrict__ sp,
                                 const float* __restrict__ ep,
                                 const float* __restrict__ K,
                                 const float* __restrict__ trans,
                                 const float* __restrict__ imgs,
                                 int n_edges, int num_src, float upscale,
                                 int W, int H, int param_blocks)
{
    int blk = blockIdx.x;
    if (blk == 0) {
        __shared__ int ssum[256];
        int tid = threadIdx.x;
        int chunk = (n_edges + 255) / 256;
        int lo = min(tid * chunk, n_edges);
        int hi = min(lo + chunk, n_edges);
        int local = 0;
        for (int i = lo; i < hi; i++) local += npe[i];
        ssum[tid] = local;
        __syncthreads();
        for (int d = 1; d < 256; d <<= 1) {
            int t = (tid >= d) ? ssum[tid - d] : 0;
            __syncthreads();
            ssum[tid] += t;
            __syncthreads();
        }
        int run = ssum[tid] - local;
        for (int i = lo; i < hi; i++) { g_begin[i] = run; run += npe[i]; }
        return;
    }
    if (blk <= param_blocks) {
        int e = (blk - 1) * blockDim.x + threadIdx.x;
        if (e >= n_edges) return;
        float sx = sp[3 * e], sy = sp[3 * e + 1], sz = sp[3 * e + 2];
        float tx = ep[3 * e], ty = ep[3 * e + 1], tz = ep[3 * e + 2];
        {
            float pzs = K[6] * sx + K[7] * sy + K[8] * sz;
            float us  = (K[0] * sx + K[1] * sy + K[2] * sz) / (pzs + 1e-6f);
            float vs  = (K[3] * sx + K[4] * sy + K[5] * sz) / (pzs + 1e-6f);
            float pzt = K[6] * tx + K[7] * ty + K[8] * tz;
            float ut  = (K[0] * tx + K[1] * ty + K[2] * tz) / (pzt + 1e-6f);
            float vt  = (K[3] * tx + K[4] * ty + K[5] * tz) / (pzt + 1e-6f);
            store_prm(0, e, n_edges, us, vs, ut - us, vt - vs, upscale);
        }
        for (int s = 0; s < num_src; s++) {
            const float* T = trans + 12 * s;
            float pzs = T[8] * sx + T[9] * sy + T[10] * sz + T[11];
            float us  = (T[0] * sx + T[1] * sy + T[2] * sz + T[3]) / (pzs + 1e-6f);
            float vs  = (T[4] * sx + T[5] * sy + T[6] * sz + T[7]) / (pzs + 1e-6f);
            float pzt = T[8] * tx + T[9] * ty + T[10] * tz + T[11];
            float ut  = (T[0] * tx + T[1] * ty + T[2] * tz + T[3]) / (pzt + 1e-6f);
            float vt  = (T[4] * tx + T[5] * ty + T[6] * tz + T[7]) / (pzt + 1e-6f);
            store_prm(1 + s, e, n_edges, us, vs, ut - us, vt - vs, upscale);
        }
        return;
    }
    // tile pass: row-major -> 4-row interleaved
    int G = (H + 3) >> 2;
    int per = G * W;                      // float4 slots per image
    int nimg = num_src + 1;
    int total = nimg * per;
    int idx = (blk - 1 - param_blocks) * blockDim.x + threadIdx.x;
    if (idx >= total) return;
    int c = idx / per;
    int rem = idx - c * per;
    int g = rem / W;
    int x = rem - g * W;
    const float* img = imgs + (size_t)c * W * H;
    float4 v;
    int y0 = g * 4;
    v.x = img[(size_t)y0 * W + x];
    v.y = (y0 + 1 < H) ? img[(size_t)(y0 + 1) * W + x] : 0.f;
    v.z = (y0 + 2 < H) ? img[(size_t)(y0 + 2) * W + x] : 0.f;
    v.w = (y0 + 3 < H) ? img[(size_t)(y0 + 3) * W + x] : 0.f;
    reinterpret_cast<float4*>(g_timg)[(size_t)c * per + rem] = v;
}

// ------------------- bilinear sample on tiled layout -----------------------
// tiled idx(x,y) = (y & ~3)*W + 4x + (y & 3)
__device__ __forceinline__ float bilerp_t(const float* __restrict__ timg,
                                          float u, float v, int W, int H)
{
    float x = fmaf(u, (float)W, -0.5f);
    float y = fmaf(v, (float)H, -0.5f);
    float x0f = floorf(x), y0f = floorf(y);
    float wx = x - x0f, wy = y - y0f;
    int x0 = max((int)x0f, 0);          // floor <= W-1 guaranteed (u < 1)
    int x1 = min(x0 + 1, W - 1);
    int y0 = max((int)y0f, 0);
    int y1 = min(y0 + 1, H - 1);
    int base0 = (y0 & ~3) * W + (y0 & 3);
    int base1 = (y1 & ~3) * W + (y1 & 3);
    int xs0 = x0 << 2, xs1 = x1 << 2;
    float v00 = __ldg(timg + (base0 + xs0));
    float v01 = __ldg(timg + (base0 + xs1));
    float v10 = __ldg(timg + (base1 + xs0));
    float v11 = __ldg(timg + (base1 + xs1));
    float top = fmaf(wx, v01 - v00, v00);
    float bot = fmaf(wx, v11 - v10, v10);
    return fmaf(wy, bot - top, top);
}

// ----------- point kernel: block/edge, 128 thr, 2 points/thread ------------
__global__ void __launch_bounds__(128, 9)
point_kernel(const int* __restrict__ npe,
             float* __restrict__ out_loss, float* __restrict__ out_mask,
             float* __restrict__ out_black,
             float* __restrict__ out_p2d1, float* __restrict__ out_p2d2,
             int W, int H, int n_edges, int P)
{
    int e = blockIdx.x;
    int tid = threadIdx.x;

    __shared__ float4 sprm4[10];    // 5 cams x {p0x,p0y,dx,dy | ux,uy,-,-}
    __shared__ float redf[4][5];
    __shared__ unsigned redm[4];

    if (tid < 10) {
        int c = tid >> 1, half = tid & 1;
        sprm4[tid] = g_params4[((size_t)c * n_edges + e) * 2 + half];
    }
    __syncthreads();

    int b = g_begin[e];
    int n = npe[e];
    float inv_nh1 = 1.0f / (float)(n / NHV2 - 1);
    const int tstride = ((H + 3) >> 2) * 4 * W;

    float ls0 = 0.f, ls1 = 0.f, ls2 = 0.f, ls3 = 0.f;
    float bc = 0.f;
    unsigned m = (1u << NS) - 1u;

    float4* o1 = reinterpret_cast<float4*>(out_p2d1) + (b >> 1);
    float4* o2 = reinterpret_cast<float4*>(out_p2d2) + (b >> 1);
    const int strideP = P >> 1;

    int npair = n >> 1;
    // incremental (h, jj): r = h*10 + jj, r advances by 128 = 12*10 + 8
    int h  = tid / 10;
    int jj = tid - h * 10;
    for (int r = tid; r < npair; r += 128) {
        float cx = (float)h * inv_nh1;
        float base = (float)(2 * jj + ((jj < 5) ? -9 : -10));
        float cy0 = base * (1.0f / 9.0f);
        float cy1 = (base + 1.0f) * (1.0f / 9.0f);

        // reference camera (LDS.128 broadcast)
        float4 qa = sprm4[0], qb = sprm4[1];
        float u0 = fmaf(qa.z, cx, fmaf(qb.x, cy0, qa.x));
        float v0 = fmaf(qa.w, cx, fmaf(qb.y, cy0, qa.y));
        float u1 = fmaf(qa.z, cx, fmaf(qb.x, cy1, qa.x));
        float v1 = fmaf(qa.w, cx, fmaf(qb.y, cy1, qa.y));
        bool vm1a = (u0 > 0.f) & (u0 < 1.f) & (v0 > 0.f) & (v0 < 1.f);
        bool vm1b = (u1 > 0.f) & (u1 < 1.f) & (v1 > 0.f) & (v1 < 1.f);
        u0 = fminf(fmaxf(u0, 0.f), 0.999999f);
        v0 = fminf(fmaxf(v0, 0.f), 0.999999f);
        u1 = fminf(fmaxf(u1, 0.f), 0.999999f);
        v1 = fminf(fmaxf(v1, 0.f), 0.999999f);
        o1[r] = make_float4(u0, v0, u1, v1);
        float s1a = bilerp_t(g_timg, u0, v0, W, H);
        float s1b = bilerp_t(g_timg, u1, v1, W, H);
        if (s1a < 0.01f) bc += 1.f;
        if (s1b < 0.01f) bc += 1.f;

#pragma unroll
        for (int s = 0; s < NS; s++) {
            float4 pa = sprm4[2 * (s + 1)], pb = sprm4[2 * (s + 1) + 1];
            float ua = fmaf(pa.z, cx, fmaf(pb.x, cy0, pa.x));
            float va = fmaf(pa.w, cx, fmaf(pb.y, cy0, pa.y));
            float ub = fmaf(pa.z, cx, fmaf(pb.x, cy1, pa.x));
            float vb = fmaf(pa.w, cx, fmaf(pb.y, cy1, pa.y));
            bool oka = vm1a & (ua > 0.f) & (ua < 1.f) & (va > 0.f) & (va < 1.f);
            bool okb = vm1b & (ub > 0.f) & (ub < 1.f) & (vb > 0.f) & (vb < 1.f);
            ua = fminf(fmaxf(ua, 0.f), 0.999999f);
            va = fminf(fmaxf(va, 0.f), 0.999999f);
            ub = fminf(fmaxf(ub, 0.f), 0.999999f);
            vb = fminf(fmaxf(vb, 0.f), 0.999999f);
            o2[s * strideP + r] = make_float4(ua, va, ub, vb);
            const float* img = g_timg + (s + 1) * tstride;
            float s2a = bilerp_t(img, ua, va, W, H);
            float s2b = bilerp_t(img, ub, vb, W, H);
            float da = s2a - s1a;
            float db = s2b - s1b;
            float acc = fmaf(da, da, db * db);
            if (s == 0) ls0 += acc;
            else if (s == 1) ls1 += acc;
            else if (s == 2) ls2 += acc;
            else ls3 += acc;
            if (!(oka && okb)) m &= ~(1u << s);
        }

        jj += 8;
        if (jj >= 10) { jj -= 10; h += 13; } else { h += 12; }
    }

    // warp + block reduce
#pragma unroll
    for (int off = 16; off > 0; off >>= 1) {
        ls0 += __shfl_down_sync(0xFFFFFFFFu, ls0, off);
        ls1 += __shfl_down_sync(0xFFFFFFFFu, ls1, off);
        ls2 += __shfl_down_sync(0xFFFFFFFFu, ls2, off);
        ls3 += __shfl_down_sync(0xFFFFFFFFu, ls3, off);
        bc  += __shfl_down_sync(0xFFFFFFFFu, bc, off);
        m   &= __shfl_down_sync(0xFFFFFFFFu, m, off);
    }
    int lane = tid & 31, warp = tid >> 5;
    if (lane == 0) {
        redf[warp][0] = ls0; redf[warp][1] = ls1;
        redf[warp][2] = ls2; redf[warp][3] = ls3;
        redf[warp][4] = bc;
        redm[warp] = m;
    }
    __syncthreads();
    if (tid == 0) {
        float tls[NS] = {0.f, 0.f, 0.f, 0.f};
        float tbc = 0.f;
        unsigned tm = (1u << NS) - 1u;
        for (int w = 0; w < 4; w++) {
#pragma unroll
            for (int s = 0; s < NS; s++) tls[s] += redf[w][s];
            tbc += redf[w][4];
            tm &= redm[w];
        }
        float cnt = (float)n;
#pragma unroll
        for (int s = 0; s < NS; s++) {
            out_loss[s * n_edges + e] = tls[s] / cnt;
            out_mask[s * n_edges + e] = ((tm >> s) & 1u) ? 1.f : 0.f;
        }
        out_black[e] = ((tbc / cnt) > 0.5f) ? 1.f : 0.f;
    }
}

// ---------------------------------------------------------------------------
extern "C" void kernel_launch(void* const* d_in, const int* in_sizes, int n_in,
                              void* d_out, int out_size)
{
    const float* start = (const float*)d_in[0];
    const float* end_p = (const float*)d_in[1];
    const float* imgs  = (const float*)d_in[2];
    const float* trans = (const float*)d_in[3];
    const float* K     = (const float*)d_in[4];
    const int*   npe   = (const int*)d_in[8];
    float* out = (float*)d_out;

    int n_edges = in_sizes[0] / 3;
    int P       = in_sizes[5];
    int num_src = in_sizes[3] / 12;  // 4
    int nimg    = num_src + 1;
    long long hw = (long long)in_sizes[2] / nimg;
    int W = (int)(sqrt((double)hw) + 0.5);
    int H = (int)(hw / W);

    float* out_loss  = out;
    float* out_mask  = out_loss + (size_t)num_src * n_edges;
    float* out_black = out_mask + (size_t)num_src * n_edges;
    float* out_p2d1  = out_black + n_edges;
    float* out_p2d2  = out_p2d1 + 2 * (size_t)P;

    int param_blocks = (n_edges + 255) / 256;
    int G = (H + 3) >> 2;
    int tile_total = nimg * G * W;
    int tile_blocks = (tile_total + 255) / 256;
    prep_tile_kernel<<<1 + param_blocks + tile_blocks, 256>>>(
        npe, start, end_p, K, trans, imgs,
        n_edges, num_src, 10.0f / (float)W, W, H, param_blocks);
    point_kernel<<<n_edges, 128>>>(npe,
                                   out_loss, out_mask, out_black,
                                   out_p2d1, out_p2d2,
                                   W, H, n_edges, P);
}